// round 1
// baseline (speedup 1.0000x reference)
#include <cuda_runtime.h>
#include <cuda_bf16.h>
#include <cstdint>

// Problem constants (fixed shapes).
#define BB 16
#define DD 2048
#define LL 512
#define NN (BB * LL)   // 8192 GEMM rows (b,t)

// Scratch (allocation-free rule: __device__ globals).
__device__ float g_P[(size_t)NN * DD];     // 64 MB, layout [b][t][p]
__device__ float g_WT[(size_t)DD * DD];    // 16 MB, WT[h][p] = w_in[p][h]

// ---------------------------------------------------------------------------
// Kernel 1: transpose w_in [p][h] -> WT [h][p]
// ---------------------------------------------------------------------------
__global__ void transpose_kernel(const float* __restrict__ in, float* __restrict__ out) {
    __shared__ float tile[32][33];
    int x = blockIdx.x * 32 + threadIdx.x;  // h
    int y = blockIdx.y * 32 + threadIdx.y;  // p
#pragma unroll
    for (int j = 0; j < 32; j += 8)
        tile[threadIdx.y + j][threadIdx.x] = in[(size_t)(y + j) * DD + x];
    __syncthreads();
    int x2 = blockIdx.y * 32 + threadIdx.x; // p
    int y2 = blockIdx.x * 32 + threadIdx.y; // h
#pragma unroll
    for (int j = 0; j < 32; j += 8)
        out[(size_t)(y2 + j) * DD + x2] = tile[threadIdx.x][threadIdx.y + j];
}

// ---------------------------------------------------------------------------
// Kernel 2: SGEMM  P[n][m] = sum_k U[n][k] * WT[k][m]
//   U[n][k] = u[(b*DD + k)*LL + t],  n = b*LL + t
// 128x128 block tile, TK=16, 256 threads, 8x8 microtile, reg prefetch.
// ---------------------------------------------------------------------------
#define TK 16

__global__ __launch_bounds__(256, 2)
void sgemm_kernel(const float* __restrict__ U, const float* __restrict__ WT,
                  float* __restrict__ P) {
    __shared__ float As[TK][128];  // [k][n_local]
    __shared__ float Bs[TK][128];  // [k][m_local]

    const int tid = threadIdx.x;
    const int m0 = blockIdx.x * 128;
    const int n0 = blockIdx.y * 128;
    const int b  = n0 >> 9;         // n0 / 512  (128 | 512, tile never crosses batch)
    const int t0 = n0 & 511;

    // Per-thread load coords (2 float4 per matrix per tile).
    int lk[2], lx[2];
#pragma unroll
    for (int i = 0; i < 2; ++i) {
        int id = tid + i * 256;
        lk[i] = id >> 5;          // 0..15
        lx[i] = (id & 31) * 4;    // 0..124
    }

    const float* Aptr = U + ((size_t)b * DD) * LL + t0;  // + k*LL + x
    const float* Bptr = WT + m0;                         // + k*DD + x

    float4 ra[2], rb[2];
#pragma unroll
    for (int i = 0; i < 2; ++i) {
        ra[i] = *(const float4*)(Aptr + (size_t)lk[i] * LL + lx[i]);
        rb[i] = *(const float4*)(Bptr + (size_t)lk[i] * DD + lx[i]);
    }

    float acc[8][8];
#pragma unroll
    for (int i = 0; i < 8; ++i)
#pragma unroll
        for (int j = 0; j < 8; ++j) acc[i][j] = 0.f;

    const int ty = tid >> 4;   // n sub-row group
    const int tx = tid & 15;   // m sub-col group

    const int KT = DD / TK;    // 128 tiles
    for (int kt = 0; kt < KT; ++kt) {
#pragma unroll
        for (int i = 0; i < 2; ++i) {
            *(float4*)&As[lk[i]][lx[i]] = ra[i];
            *(float4*)&Bs[lk[i]][lx[i]] = rb[i];
        }
        __syncthreads();

        if (kt + 1 < KT) {
            const int kb = (kt + 1) * TK;
#pragma unroll
            for (int i = 0; i < 2; ++i) {
                ra[i] = *(const float4*)(Aptr + (size_t)(kb + lk[i]) * LL + lx[i]);
                rb[i] = *(const float4*)(Bptr + (size_t)(kb + lk[i]) * DD + lx[i]);
            }
        }

#pragma unroll
        for (int kk = 0; kk < TK; ++kk) {
            float4 a0 = *(const float4*)&As[kk][ty * 8];
            float4 a1 = *(const float4*)&As[kk][ty * 8 + 4];
            float4 b0 = *(const float4*)&Bs[kk][tx * 8];
            float4 b1 = *(const float4*)&Bs[kk][tx * 8 + 4];
            float an[8] = {a0.x, a0.y, a0.z, a0.w, a1.x, a1.y, a1.z, a1.w};
            float bm[8] = {b0.x, b0.y, b0.z, b0.w, b1.x, b1.y, b1.z, b1.w};
#pragma unroll
            for (int i = 0; i < 8; ++i)
#pragma unroll
                for (int j = 0; j < 8; ++j)
                    acc[i][j] = fmaf(an[i], bm[j], acc[i][j]);
        }
        __syncthreads();
    }

    // Epilogue: P[(n0+ty*8+i)][m0+tx*8+j]
#pragma unroll
    for (int i = 0; i < 8; ++i) {
        float* row = P + (size_t)(n0 + ty * 8 + i) * DD + m0 + tx * 8;
        float4 v0 = make_float4(acc[i][0], acc[i][1], acc[i][2], acc[i][3]);
        float4 v1 = make_float4(acc[i][4], acc[i][5], acc[i][6], acc[i][7]);
        *(float4*)(row)     = v0;
        *(float4*)(row + 4) = v1;
    }
}

// ---------------------------------------------------------------------------
// Kernel 3: recurrence scan + transposed write
//   x_t = tanh(P[b,t,p] + diag(w_hh)[p]*x_{t-1} + bias[p]);  out[b,p,t] = x_t
// grid (DD/256, BB), 256 threads. Coalesced P reads; smem-staged coalesced
// out writes (tile of 32 timesteps).
// ---------------------------------------------------------------------------
__global__ __launch_bounds__(256)
void scan_kernel(const float* __restrict__ whh, const float* __restrict__ bias,
                 float* __restrict__ out) {
    __shared__ float tile[256][33];  // [p_local][t_local], padded

    const int b   = blockIdx.y;
    const int p0  = blockIdx.x * 256;
    const int tid = threadIdx.x;
    const int p   = p0 + tid;
    const int lane = tid & 31;
    const int wid  = tid >> 5;

    const float d  = whh[(size_t)p * DD + p];
    const float bi = bias[p];
    const float* Pb = g_P + (size_t)b * LL * DD;

    float x = 0.f;
    for (int t0 = 0; t0 < LL; t0 += 32) {
#pragma unroll
        for (int tt = 0; tt < 32; ++tt) {
            float pre = Pb[(size_t)(t0 + tt) * DD + p] + d * x + bi;
            x = tanhf(pre);
            tile[tid][tt] = x;
        }
        __syncthreads();
#pragma unroll 8
        for (int pp = 0; pp < 32; ++pp) {
            int pl = wid * 32 + pp;
            out[((size_t)(b * DD + p0 + pl)) * LL + t0 + lane] = tile[pl][lane];
        }
        __syncthreads();
    }
}

// ---------------------------------------------------------------------------
extern "C" void kernel_launch(void* const* d_in, const int* in_sizes, int n_in,
                              void* d_out, int out_size) {
    const float* u    = (const float*)d_in[0];  // [B, D, L]
    const float* w_in = (const float*)d_in[1];  // [D, D]
    const float* w_hh = (const float*)d_in[2];  // [D, D]
    const float* bias = (const float*)d_in[3];  // [D]
    float* out = (float*)d_out;                 // [B, D, L]

    float* P;  cudaGetSymbolAddress((void**)&P,  g_P);
    float* WT; cudaGetSymbolAddress((void**)&WT, g_WT);

    // 1. Transpose w_in -> WT[h][p]
    {
        dim3 grid(DD / 32, DD / 32), block(32, 8);
        transpose_kernel<<<grid, block>>>(w_in, WT);
    }
    // 2. GEMM: P[b][t][p] = sum_h u[b,h,t] * w_in[p,h]
    {
        dim3 grid(DD / 128, NN / 128);  // (16, 64)
        sgemm_kernel<<<grid, 256>>>(u, WT, P);
    }
    // 3. Scan + transpose to out[b][p][t]
    {
        dim3 grid(DD / 256, BB);        // (8, 16)
        scan_kernel<<<grid, 256>>>(w_hh, bias, out);
    }
}

// round 3
// speedup vs baseline: 2.0513x; 2.0513x over previous
#include <cuda_runtime.h>
#include <cuda_bf16.h>
#include <cstdint>

#define BB 16
#define DD 2048
#define LL 512
#define NN 8192
#define KK 6144          // 3 K-blocks: [u_hi.w_hi | u_hi.w_lo | u_lo.w_hi]
#define NCH 96           // KK / 64

// Scratch (__device__ globals; allocation-free rule)
__device__ float g_P[(size_t)NN * DD];              // 64 MB  P[n][m]
__device__ __nv_bfloat16 g_A2[(size_t)NN * KK];     // 96 MB  A2[n][k2]
__device__ __nv_bfloat16 g_B2[(size_t)DD * KK];     // 24 MB  B2[m][k2]

// ---------------------------------------------------------------------------
// sm_80-compatible PTX helpers (NO tcgen05 — ptxas target here is sm_103 base)
// ---------------------------------------------------------------------------
__device__ __forceinline__ uint32_t s2u(const void* p) {
    return (uint32_t)__cvta_generic_to_shared(const_cast<void*>(p));
}
__device__ __forceinline__ void cp16(uint32_t dst, const void* src) {
    asm volatile("cp.async.cg.shared.global [%0], [%1], 16;" :: "r"(dst), "l"(src));
}
#define CP_COMMIT() asm volatile("cp.async.commit_group;" ::: "memory")
#define CP_WAIT1()  asm volatile("cp.async.wait_group 1;" ::: "memory")

__device__ __forceinline__ void ldsm4(uint32_t* r, uint32_t addr) {
    asm volatile("ldmatrix.sync.aligned.m8n8.x4.shared.b16 {%0,%1,%2,%3}, [%4];"
                 : "=r"(r[0]), "=r"(r[1]), "=r"(r[2]), "=r"(r[3]) : "r"(addr));
}
__device__ __forceinline__ void mma16816(float* c, const uint32_t* a,
                                         uint32_t b0, uint32_t b1) {
    asm volatile(
        "mma.sync.aligned.m16n8k16.row.col.f32.bf16.bf16.f32 "
        "{%0,%1,%2,%3}, {%4,%5,%6,%7}, {%8,%9}, {%0,%1,%2,%3};"
        : "+f"(c[0]), "+f"(c[1]), "+f"(c[2]), "+f"(c[3])
        : "r"(a[0]), "r"(a[1]), "r"(a[2]), "r"(a[3]), "r"(b0), "r"(b1));
}

// ---------------------------------------------------------------------------
// conv_w: B2[m] = [w_hi | w_lo | w_hi]
// ---------------------------------------------------------------------------
__global__ void conv_w_kernel(const float* __restrict__ w, __nv_bfloat16* __restrict__ B2) {
    const int k = blockIdx.x * 256 + threadIdx.x;
    const int m = blockIdx.y;
    float v = w[(size_t)m * DD + k];
    __nv_bfloat16 hi = __float2bfloat16(v);
    __nv_bfloat16 lo = __float2bfloat16(v - __bfloat162float(hi));
    __nv_bfloat16* row = B2 + (size_t)m * KK;
    row[k] = hi;
    row[DD + k] = lo;
    row[2 * DD + k] = hi;
}

// ---------------------------------------------------------------------------
// conv_u: transpose u[b][h][t] -> A2[n=b*L+t] = [u_hi | u_hi | u_lo]
// ---------------------------------------------------------------------------
__global__ void conv_u_kernel(const float* __restrict__ u, __nv_bfloat16* __restrict__ A2) {
    __shared__ float tile[32][33];
    const int b = blockIdx.z;
    const int t0 = blockIdx.x * 32, h0 = blockIdx.y * 32;
    const int tx = threadIdx.x, ty = threadIdx.y;
    const float* up = u + ((size_t)b * DD + h0) * LL + t0;
#pragma unroll
    for (int j = 0; j < 32; j += 8)
        tile[ty + j][tx] = up[(size_t)(ty + j) * LL + tx];   // [h_loc][t_loc]
    __syncthreads();
#pragma unroll
    for (int j = 0; j < 32; j += 8) {
        float v = tile[tx][ty + j];                // h = h0+tx, t = t0+ty+j
        __nv_bfloat16 hi = __float2bfloat16(v);
        __nv_bfloat16 lo = __float2bfloat16(v - __bfloat162float(hi));
        __nv_bfloat16* row = A2 + ((size_t)b * LL + t0 + ty + j) * KK;
        row[h0 + tx] = hi;
        row[DD + h0 + tx] = hi;
        row[2 * DD + h0 + tx] = lo;
    }
}

// ---------------------------------------------------------------------------
// HMMA GEMM: P[n][m] = sum_k A2[n][k] * B2[m][k]
// CTA 256n x 128m, 8 warps (4n x 2m), warp tile 64x64, K-chunk 64,
// 3-stage cp.async, SW128 swizzle, ldmatrix + mma.sync.m16n8k16 bf16.
// ---------------------------------------------------------------------------
#define STB 49152                 // stage: A 256*128B (32K) + B 128*128B (16K)
#define SMEMG (3 * STB)           // 144 KB

__global__ __launch_bounds__(256, 1)
void gemm_kernel(const __nv_bfloat16* __restrict__ A,
                 const __nv_bfloat16* __restrict__ Bm,
                 float* __restrict__ P) {
    extern __shared__ char smem[];
    const uint32_t s0 = s2u(smem);
    const int tid = threadIdx.x;
    const int wid = tid >> 5, lane = tid & 31;
    const int wn = wid & 3, wm = wid >> 2;      // warp coords: 4n x 2m
    const int m0 = blockIdx.x * 128;
    const int n0 = blockIdx.y * 256;

    const __nv_bfloat16* Ab = A + (size_t)n0 * KK;
    const __nv_bfloat16* Bb = Bm + (size_t)m0 * KK;

    auto load_chunk = [&](int stage, int ch) {
        const uint32_t sa = s0 + stage * STB;
        const int kb = ch * 64;
#pragma unroll
        for (int i = 0; i < 8; ++i) {           // A: 256 rows x 8 x16B
            int idx = tid + i * 256;
            int r = idx >> 3, c = idx & 7;
            uint32_t off = (uint32_t)r * 128u + (uint32_t)c * 16u;
            cp16(sa + (off ^ ((off >> 3) & 0x70)), Ab + (size_t)r * KK + kb + c * 8);
        }
#pragma unroll
        for (int i = 0; i < 4; ++i) {           // B: 128 rows x 8 x16B
            int idx = tid + i * 256;
            int r = idx >> 3, c = idx & 7;
            uint32_t off = (uint32_t)r * 128u + (uint32_t)c * 16u;
            cp16(sa + 32768u + (off ^ ((off >> 3) & 0x70)), Bb + (size_t)r * KK + kb + c * 8);
        }
    };

    load_chunk(0, 0); CP_COMMIT();
    load_chunk(1, 1); CP_COMMIT();

    // Precomputed ldmatrix lane addressing.
    // A frag ni (16x16): row = wn*64 + ni*16 + (lane&15); koff = (lane>>4)*16
    uint32_t a_rbase[4], a_xm[4];
#pragma unroll
    for (int ni = 0; ni < 4; ++ni) {
        uint32_t row = wn * 64 + ni * 16 + (lane & 15);
        a_rbase[ni] = row * 128u;
        a_xm[ni] = (row & 7) << 4;
    }
    const uint32_t a_koff = (lane >> 4) * 16;
    // B frag bi (m16 x k16): lanes 0-7: m0-7/k0; 8-15: m0-7/k16B; 16-23: m8-15/k0; 24-31: m8-15/k16B
    uint32_t b_rbase[4], b_xm[4];
    {
        uint32_t mrow_in16 = (lane & 7) + ((lane >> 4) << 3);
#pragma unroll
        for (int bi = 0; bi < 4; ++bi) {
            uint32_t row = wm * 64 + bi * 16 + mrow_in16;
            b_rbase[bi] = 32768u + row * 128u;
            b_xm[bi] = (row & 7) << 4;
        }
    }
    const uint32_t b_koff = ((lane >> 3) & 1) * 16;

    float c[4][8][4];
#pragma unroll
    for (int i = 0; i < 4; ++i)
#pragma unroll
        for (int j = 0; j < 8; ++j)
#pragma unroll
            for (int v = 0; v < 4; ++v) c[i][j][v] = 0.f;

    for (int ch = 0; ch < NCH; ++ch) {
        CP_WAIT1();
        __syncthreads();
        int nc = ch + 2;
        if (nc < NCH) load_chunk((nc) % 3, nc);
        CP_COMMIT();

        const uint32_t sa = s0 + (ch % 3) * STB;
#pragma unroll
        for (int ks = 0; ks < 4; ++ks) {
            uint32_t a[4][4], b[4][4];
#pragma unroll
            for (int ni = 0; ni < 4; ++ni)
                ldsm4(a[ni], sa + a_rbase[ni] + ((ks * 32 + a_koff) ^ a_xm[ni]));
#pragma unroll
            for (int bi = 0; bi < 4; ++bi)
                ldsm4(b[bi], sa + b_rbase[bi] + ((ks * 32 + b_koff) ^ b_xm[bi]));
#pragma unroll
            for (int ni = 0; ni < 4; ++ni)
#pragma unroll
                for (int bi = 0; bi < 4; ++bi) {
                    mma16816(c[ni][bi * 2],     a[ni], b[bi][0], b[bi][1]);
                    mma16816(c[ni][bi * 2 + 1], a[ni], b[bi][2], b[bi][3]);
                }
        }
    }

    // Epilogue: direct register -> global
    const int q = lane >> 2, qr = lane & 3;
#pragma unroll
    for (int ni = 0; ni < 4; ++ni) {
        int row = n0 + wn * 64 + ni * 16 + q;
#pragma unroll
        for (int mi = 0; mi < 8; ++mi) {
            int col = m0 + wm * 64 + mi * 8 + qr * 2;
            float2* p0 = (float2*)(P + (size_t)row * DD + col);
            float2* p1 = (float2*)(P + (size_t)(row + 8) * DD + col);
            *p0 = make_float2(c[ni][mi][0], c[ni][mi][1]);
            *p1 = make_float2(c[ni][mi][2], c[ni][mi][3]);
        }
    }
}

// ---------------------------------------------------------------------------
// Scan: x_t = tanh(P[b,t,p] + d_p*x_{t-1} + bias_p);  out[b,p,t]
// ---------------------------------------------------------------------------
__device__ __forceinline__ float tanh_fast(float x) {
    float r;
    asm("tanh.approx.f32 %0, %1;" : "=f"(r) : "f"(x));
    return r;
}

__global__ __launch_bounds__(256)
void scan_kernel(const float* __restrict__ whh, const float* __restrict__ bias,
                 const float* __restrict__ P, float* __restrict__ out) {
    __shared__ float tile[256][33];
    const int b = blockIdx.y;
    const int p0 = blockIdx.x * 256;
    const int tid = threadIdx.x;
    const int p = p0 + tid;
    const int lane = tid & 31, wrp = tid >> 5;
    const float d = whh[(size_t)p * DD + p];
    const float bi = bias[p];
    const float* Pb = P + (size_t)b * LL * DD + p;

    float x = 0.f;
    for (int t0 = 0; t0 < LL; t0 += 32) {
        float pv[32];
#pragma unroll
        for (int tt = 0; tt < 32; ++tt)
            pv[tt] = Pb[(size_t)(t0 + tt) * DD] + bi;
#pragma unroll
        for (int tt = 0; tt < 32; ++tt) {
            float pre = fmaf(d, x, pv[tt]);
            float t;
            if (fabsf(pre) < 5.0f) t = tanh_fast(pre);
            else t = copysignf(1.0f, pre);     // |tanh|>0.99990 -> err < 1e-4
            x = t;
            tile[tid][tt] = x;
        }
        __syncthreads();
#pragma unroll 8
        for (int pp = 0; pp < 32; ++pp) {
            int pl = wrp * 32 + pp;
            out[((size_t)b * DD + p0 + pl) * LL + t0 + lane] = tile[pl][lane];
        }
        __syncthreads();
    }
}

// ---------------------------------------------------------------------------
extern "C" void kernel_launch(void* const* d_in, const int* in_sizes, int n_in,
                              void* d_out, int out_size) {
    const float* u    = (const float*)d_in[0];
    const float* w_in = (const float*)d_in[1];
    const float* w_hh = (const float*)d_in[2];
    const float* bias = (const float*)d_in[3];
    float* out = (float*)d_out;

    float* P;          cudaGetSymbolAddress((void**)&P,  g_P);
    __nv_bfloat16* A2; cudaGetSymbolAddress((void**)&A2, g_A2);
    __nv_bfloat16* B2; cudaGetSymbolAddress((void**)&B2, g_B2);

    conv_w_kernel<<<dim3(DD / 256, DD), 256>>>(w_in, B2);
    conv_u_kernel<<<dim3(LL / 32, DD / 32, BB), dim3(32, 8)>>>(u, A2);

    cudaFuncSetAttribute(gemm_kernel, cudaFuncAttributeMaxDynamicSharedMemorySize, SMEMG);
    gemm_kernel<<<dim3(DD / 128, NN / 256), 256, SMEMG>>>(A2, B2, P);

    scan_kernel<<<dim3(DD / 256, BB), 256>>>(w_hh, bias, P, out);
}

// round 4
// speedup vs baseline: 2.5991x; 1.2671x over previous
#include <cuda_runtime.h>
#include <cuda_bf16.h>
#include <cstdint>

#define BB 16
#define DD 2048
#define LL 512
#define NN 8192
#define KK 6144          // 3 K-blocks: [u_hi.w_hi | u_hi.w_lo | u_lo.w_hi]
#define NCH 96           // KK / 64

// Scratch (__device__ globals; allocation-free rule)
__device__ float g_P[(size_t)NN * DD];              // 64 MB  P[n][m]
__device__ __nv_bfloat16 g_A2[(size_t)NN * KK];     // 96 MB  A2[n][k2]
__device__ __nv_bfloat16 g_B2[(size_t)DD * KK];     // 24 MB  B2[m][k2]

// ---------------------------------------------------------------------------
// sm_80-compatible PTX helpers (no tcgen05 — ptxas target is sm_103 base)
// ---------------------------------------------------------------------------
__device__ __forceinline__ uint32_t s2u(const void* p) {
    return (uint32_t)__cvta_generic_to_shared(const_cast<void*>(p));
}
__device__ __forceinline__ void cp16(uint32_t dst, const void* src) {
    asm volatile("cp.async.cg.shared.global [%0], [%1], 16;" :: "r"(dst), "l"(src));
}
#define CP_COMMIT() asm volatile("cp.async.commit_group;" ::: "memory")
#define CP_WAIT1()  asm volatile("cp.async.wait_group 1;" ::: "memory")

__device__ __forceinline__ void ldsm4(uint32_t* r, uint32_t addr) {
    asm volatile("ldmatrix.sync.aligned.m8n8.x4.shared.b16 {%0,%1,%2,%3}, [%4];"
                 : "=r"(r[0]), "=r"(r[1]), "=r"(r[2]), "=r"(r[3]) : "r"(addr));
}
__device__ __forceinline__ void mma16816(float* c, const uint32_t* a,
                                         uint32_t b0, uint32_t b1) {
    asm volatile(
        "mma.sync.aligned.m16n8k16.row.col.f32.bf16.bf16.f32 "
        "{%0,%1,%2,%3}, {%4,%5,%6,%7}, {%8,%9}, {%0,%1,%2,%3};"
        : "+f"(c[0]), "+f"(c[1]), "+f"(c[2]), "+f"(c[3])
        : "r"(a[0]), "r"(a[1]), "r"(a[2]), "r"(a[3]), "r"(b0), "r"(b1));
}

// ---------------------------------------------------------------------------
// conv_w: B2[m] = [w_hi | w_lo | w_hi]
// ---------------------------------------------------------------------------
__global__ void conv_w_kernel(const float* __restrict__ w, __nv_bfloat16* __restrict__ B2) {
    const int k = blockIdx.x * 256 + threadIdx.x;
    const int m = blockIdx.y;
    float v = w[(size_t)m * DD + k];
    __nv_bfloat16 hi = __float2bfloat16(v);
    __nv_bfloat16 lo = __float2bfloat16(v - __bfloat162float(hi));
    __nv_bfloat16* row = B2 + (size_t)m * KK;
    row[k] = hi;
    row[DD + k] = lo;
    row[2 * DD + k] = hi;
}

// ---------------------------------------------------------------------------
// conv_u: transpose u[b][h][t] -> A2[n=b*L+t] = [u_hi | u_hi | u_lo]
// ---------------------------------------------------------------------------
__global__ void conv_u_kernel(const float* __restrict__ u, __nv_bfloat16* __restrict__ A2) {
    __shared__ float tile[32][33];
    const int b = blockIdx.z;
    const int t0 = blockIdx.x * 32, h0 = blockIdx.y * 32;
    const int tx = threadIdx.x, ty = threadIdx.y;
    const float* up = u + ((size_t)b * DD + h0) * LL + t0;
#pragma unroll
    for (int j = 0; j < 32; j += 8)
        tile[ty + j][tx] = up[(size_t)(ty + j) * LL + tx];   // [h_loc][t_loc]
    __syncthreads();
#pragma unroll
    for (int j = 0; j < 32; j += 8) {
        float v = tile[tx][ty + j];                // h = h0+tx, t = t0+ty+j
        __nv_bfloat16 hi = __float2bfloat16(v);
        __nv_bfloat16 lo = __float2bfloat16(v - __bfloat162float(hi));
        __nv_bfloat16* row = A2 + ((size_t)b * LL + t0 + ty + j) * KK;
        row[h0 + tx] = hi;
        row[DD + h0 + tx] = hi;
        row[2 * DD + h0 + tx] = lo;
    }
}

// ---------------------------------------------------------------------------
// HMMA GEMM: P[n][m] = sum_k A2[n][k] * B2[m][k]
// CTA 128n x 128m, 8 warps (2n x 4m), warp tile 64x32, K-chunk 64,
// 3-stage cp.async (32KB/stage, 96KB total -> 2 CTAs/SM), SW128 swizzle.
// ---------------------------------------------------------------------------
#define STB 32768                 // stage: A 128*128B (16K) + B 128*128B (16K)
#define SMEMG (3 * STB)           // 96 KB

__global__ __launch_bounds__(256, 2)
void gemm_kernel(const __nv_bfloat16* __restrict__ A,
                 const __nv_bfloat16* __restrict__ Bm,
                 float* __restrict__ P) {
    extern __shared__ char smem[];
    const uint32_t s0 = s2u(smem);
    const int tid = threadIdx.x;
    const int wid = tid >> 5, lane = tid & 31;
    const int wn = wid & 1, wm = wid >> 1;      // warps: 2n x 4m
    const int m0 = blockIdx.x * 128;
    const int n0 = blockIdx.y * 128;

    const __nv_bfloat16* Ab = A + (size_t)n0 * KK;
    const __nv_bfloat16* Bb = Bm + (size_t)m0 * KK;

    auto load_chunk = [&](int stage, int ch) {
        const uint32_t sa = s0 + stage * STB;
        const int kb = ch * 64;
#pragma unroll
        for (int i = 0; i < 4; ++i) {           // A: 128 rows x 8 x16B
            int idx = tid + i * 256;
            int r = idx >> 3, c = idx & 7;
            uint32_t off = (uint32_t)r * 128u + (uint32_t)c * 16u;
            cp16(sa + (off ^ ((off >> 3) & 0x70)), Ab + (size_t)r * KK + kb + c * 8);
        }
#pragma unroll
        for (int i = 0; i < 4; ++i) {           // B: 128 rows x 8 x16B
            int idx = tid + i * 256;
            int r = idx >> 3, c = idx & 7;
            uint32_t off = (uint32_t)r * 128u + (uint32_t)c * 16u;
            cp16(sa + 16384u + (off ^ ((off >> 3) & 0x70)), Bb + (size_t)r * KK + kb + c * 8);
        }
    };

    load_chunk(0, 0); CP_COMMIT();
    load_chunk(1, 1); CP_COMMIT();

    // ldmatrix lane addressing
    uint32_t a_rbase[4], a_xm[4];
#pragma unroll
    for (int ni = 0; ni < 4; ++ni) {
        uint32_t row = wn * 64 + ni * 16 + (lane & 15);
        a_rbase[ni] = row * 128u;
        a_xm[ni] = (row & 7) << 4;
    }
    const uint32_t a_koff = (lane >> 4) * 16;
    uint32_t b_rbase[2], b_xm[2];
    {
        uint32_t mrow_in16 = (lane & 7) + ((lane >> 4) << 3);
#pragma unroll
        for (int bi = 0; bi < 2; ++bi) {
            uint32_t row = wm * 32 + bi * 16 + mrow_in16;
            b_rbase[bi] = 16384u + row * 128u;
            b_xm[bi] = (row & 7) << 4;
        }
    }
    const uint32_t b_koff = ((lane >> 3) & 1) * 16;

    float c[4][4][4];
#pragma unroll
    for (int i = 0; i < 4; ++i)
#pragma unroll
        for (int j = 0; j < 4; ++j)
#pragma unroll
            for (int v = 0; v < 4; ++v) c[i][j][v] = 0.f;

    for (int ch = 0; ch < NCH; ++ch) {
        CP_WAIT1();
        __syncthreads();                 // all warps done with stage (ch-1)%3
        int nc = ch + 2;
        if (nc < NCH) load_chunk(nc % 3, nc);
        CP_COMMIT();

        const uint32_t sa = s0 + (ch % 3) * STB;
#pragma unroll
        for (int ks = 0; ks < 4; ++ks) {
            uint32_t a[4][4], b[2][4];
#pragma unroll
            for (int ni = 0; ni < 4; ++ni)
                ldsm4(a[ni], sa + a_rbase[ni] + ((ks * 32 + a_koff) ^ a_xm[ni]));
#pragma unroll
            for (int bi = 0; bi < 2; ++bi)
                ldsm4(b[bi], sa + b_rbase[bi] + ((ks * 32 + b_koff) ^ b_xm[bi]));
#pragma unroll
            for (int ni = 0; ni < 4; ++ni)
#pragma unroll
                for (int bi = 0; bi < 2; ++bi) {
                    mma16816(c[ni][bi * 2],     a[ni], b[bi][0], b[bi][1]);
                    mma16816(c[ni][bi * 2 + 1], a[ni], b[bi][2], b[bi][3]);
                }
        }
    }

    // Epilogue: registers -> global
    const int q = lane >> 2, qr = lane & 3;
#pragma unroll
    for (int ni = 0; ni < 4; ++ni) {
        int row = n0 + wn * 64 + ni * 16 + q;
#pragma unroll
        for (int mi = 0; mi < 4; ++mi) {
            int col = m0 + wm * 32 + mi * 8 + qr * 2;
            *(float2*)(P + (size_t)row * DD + col) = make_float2(c[ni][mi][0], c[ni][mi][1]);
            *(float2*)(P + (size_t)(row + 8) * DD + col) = make_float2(c[ni][mi][2], c[ni][mi][3]);
        }
    }
}

// ---------------------------------------------------------------------------
// Scan: x_t = tanh(P[b,t,p] + d_p*x_{t-1} + bias_p);  out[b,p,t]
// 256 CTAs x 128 threads; double-buffered P prefetch.
// ---------------------------------------------------------------------------
__device__ __forceinline__ float tanh_fast(float x) {
    float r;
    asm("tanh.approx.f32 %0, %1;" : "=f"(r) : "f"(x));
    return r;
}

__global__ __launch_bounds__(128)
void scan_kernel(const float* __restrict__ whh, const float* __restrict__ bias,
                 const float* __restrict__ P, float* __restrict__ out) {
    __shared__ float tile[128][33];
    const int b = blockIdx.y;
    const int p0 = blockIdx.x * 128;
    const int tid = threadIdx.x;
    const int p = p0 + tid;
    const int lane = tid & 31, wrp = tid >> 5;
    const float d = whh[(size_t)p * DD + p];
    const float bi = bias[p];
    const float* Pb = P + (size_t)b * LL * DD + p;

    float cur[32], nxt[32];
#pragma unroll
    for (int tt = 0; tt < 32; ++tt)
        cur[tt] = Pb[(size_t)tt * DD];

    float x = 0.f;
    for (int t0 = 0; t0 < LL; t0 += 32) {
        if (t0 + 32 < LL) {
#pragma unroll
            for (int tt = 0; tt < 32; ++tt)
                nxt[tt] = Pb[(size_t)(t0 + 32 + tt) * DD];    // prefetch (MLP)
        }
#pragma unroll
        for (int tt = 0; tt < 32; ++tt) {
            float pre = fmaf(d, x, cur[tt] + bi);
            float t;
            if (fabsf(pre) < 5.0f) t = tanh_fast(pre);
            else t = copysignf(1.0f, pre);     // |tanh|>0.99990 -> err < 1e-4
            x = t;
            tile[tid][tt] = x;
        }
        __syncthreads();
#pragma unroll 8
        for (int pp = 0; pp < 32; ++pp) {
            int pl = wrp * 32 + pp;
            out[((size_t)b * DD + p0 + pl) * LL + t0 + lane] = tile[pl][lane];
        }
        __syncthreads();
#pragma unroll
        for (int tt = 0; tt < 32; ++tt) cur[tt] = nxt[tt];
    }
}

// ---------------------------------------------------------------------------
extern "C" void kernel_launch(void* const* d_in, const int* in_sizes, int n_in,
                              void* d_out, int out_size) {
    const float* u    = (const float*)d_in[0];
    const float* w_in = (const float*)d_in[1];
    const float* w_hh = (const float*)d_in[2];
    const float* bias = (const float*)d_in[3];
    float* out = (float*)d_out;

    float* P;          cudaGetSymbolAddress((void**)&P,  g_P);
    __nv_bfloat16* A2; cudaGetSymbolAddress((void**)&A2, g_A2);
    __nv_bfloat16* B2; cudaGetSymbolAddress((void**)&B2, g_B2);

    conv_w_kernel<<<dim3(DD / 256, DD), 256>>>(w_in, B2);
    conv_u_kernel<<<dim3(LL / 32, DD / 32, BB), dim3(32, 8)>>>(u, A2);

    cudaFuncSetAttribute(gemm_kernel, cudaFuncAttributeMaxDynamicSharedMemorySize, SMEMG);
    gemm_kernel<<<dim3(DD / 128, NN / 128), 256, SMEMG>>>(A2, B2, P);

    scan_kernel<<<dim3(DD / 128, BB), 128>>>(w_hh, bias, P, out);
}